// round 11
// baseline (speedup 1.0000x reference)
#include <cuda_runtime.h>
#include <math_constants.h>
#include <cstdint>

// Problem shape (fixed per reference):
//   cls_pred  [8, 80, 256, 256] f32
//   txty_pred [8,  2, 256, 256] f32
//   twth_pred [8,  2, 256, 256] f32
// Output: bbox[100,4] | score[100] | cls[100]  -> 600 f32, batch 0 only.
//
// Exact algorithm: top-100 of suppressed scores == top-100 over 5x5-local-max
// peaks. Raw logits compared (sigmoid strictly monotone). Tier-A = peaks with
// logit > THR. If nA >= 100, the 100th-best peak > THR, so the true top-100
// is a subset of tier-A (checked at runtime). Otherwise an exact full-rescan
// fallback runs in the same kernel (P(nA<100) ~ 1e-40 for N(0,1) data).

#define C_CLS   80
#define H_DIM   256
#define W_DIM   256
#define HW      (H_DIM * W_DIM)       // 65536
#define N_ALL   (C_CLS * HW)          // 5242880
#define TOPK_N  100
#define THR     3.8f
#define SEL_CAP 2048
#define A_GCAP  65536
#define V4_PT   8                      // float4 loads per thread
#define TPB     256

// Scratch. BSS zero-init; the selecting block resets counters at the end of
// every invocation, so each kernel_launch call is deterministic.
__device__ unsigned long long g_candA[A_GCAP];
__device__ unsigned long long g_candB[N_ALL];   // fallback only
__device__ int g_cntA, g_cntB, g_done;

// Order-preserving float -> unsigned transform.
__device__ __forceinline__ unsigned fkey(float f) {
    unsigned b = __float_as_uint(f);
    return (b & 0x80000000u) ? ~b : (b | 0x80000000u);
}
__device__ __forceinline__ float fkey_inv(unsigned k) {
    unsigned b = (k & 0x80000000u) ? (k & 0x7FFFFFFFu) : ~k;
    return __uint_as_float(b);
}

// Check pixel (yy, xx) of plane `b`: true iff no 5x5 neighbor exceeds c.
__device__ __forceinline__ bool is_peak(const float* __restrict__ b,
                                        int yy, int xx, float c) {
    int ylo = max(yy - 2, 0), yhi = min(yy + 2, H_DIM - 1);
    int xlo = max(xx - 2, 0), xhi = min(xx + 2, W_DIM - 1);
    float m = -CUDART_INF_F;
    for (int ny = ylo; ny <= yhi; ny++) {
        const float* row = b + ny * W_DIM;
        for (int nx = xlo; nx <= xhi; nx++)
            m = fmaxf(m, row[nx]);   // includes self; c >= m <=> peak (ties kept)
    }
    return c >= m;
}

__global__ __launch_bounds__(TPB)
void det_kernel(const float* __restrict__ cls,
                const float* __restrict__ txty,
                const float* __restrict__ twth,
                float* __restrict__ out) {
    __shared__ union {
        unsigned long long cand[SEL_CAP];   // select staging (last block only)
        unsigned           hist[4096];      // fallback scratch
    } u;
    __shared__ unsigned long long s_sel[TOPK_N];
    __shared__ unsigned long long s_best;
    __shared__ int s_last, s_ng, s_bin;

    const int tid  = threadIdx.x;
    const int lane = tid & 31;
    const int cid  = blockIdx.y;
    const float* __restrict__ base = cls + (size_t)cid * HW;
    const float4* __restrict__ base4 = (const float4*)base;

    // ---- phase 1: gated scan. 8 independent float4 loads per thread. ----
    const int g0 = blockIdx.x * (TPB * V4_PT) + tid;
    float4 v[V4_PT];
    #pragma unroll
    for (int k = 0; k < V4_PT; k++)
        v[k] = __ldg(base4 + g0 + k * TPB);

    #pragma unroll
    for (int k = 0; k < V4_PT; k++) {
        float m4 = fmaxf(fmaxf(v[k].x, v[k].y), fmaxf(v[k].z, v[k].w));
        if (__ballot_sync(0xFFFFFFFFu, m4 > THR)) {     // ~7% of warp-chunks
            const int g = g0 + k * TPB;                 // float4 index in plane
            #pragma unroll
            for (int e = 0; e < 4; e++) {
                float c = (e == 0) ? v[k].x : (e == 1) ? v[k].y
                        : (e == 2) ? v[k].z : v[k].w;
                bool isA = false;
                int sp = g * 4 + e;
                if (c > THR)
                    isA = is_peak(base, sp >> 8, sp & 255, c);
                unsigned ba = __ballot_sync(0xFFFFFFFFu, isA);
                if (ba) {
                    int p;
                    if (lane == 0) p = atomicAdd(&g_cntA, __popc(ba));
                    p = __shfl_sync(0xFFFFFFFFu, p, 0);
                    if (isA) {
                        int o = p + __popc(ba & ((1u << lane) - 1u));
                        if (o < A_GCAP) {
                            unsigned idx = ((unsigned)cid << 16) | (unsigned)sp;
                            g_candA[o] = ((unsigned long long)fkey(c) << 32) |
                                         (unsigned long long)(~idx);
                        }
                    }
                }
            }
        }
    }

    // ---- last-block-done ticket ----
    __syncthreads();
    if (tid == 0) {
        __threadfence();
        int total = gridDim.x * gridDim.y;
        s_last = (atomicAdd(&g_done, 1) == total - 1) ? 1 : 0;
    }
    __syncthreads();
    if (!s_last) return;
    __threadfence();

    const int n = g_cntA;

    if (n >= TOPK_N && n <= SEL_CAP) {
        // ---- fast exact path: O(n^2/256) rank select over ~380 candidates ----
        for (int i = tid; i < n; i += TPB) u.cand[i] = g_candA[i];
        __syncthreads();
        for (int i = tid; i < n; i += TPB) {
            unsigned long long vv = u.cand[i];
            int rank = 0;
            for (int j = 0; j < n; j++) rank += (u.cand[j] > vv);
            if (rank < TOPK_N) s_sel[rank] = vv;
        }
        __syncthreads();
        if (tid == 0) { g_cntA = 0; g_done = 0; }
    } else {
        // ---- slow exact fallback (never taken for benchmark data) ----
        for (int c2 = 0; c2 < C_CLS; c2++) {
            const float* b = cls + (size_t)c2 * HW;
            for (int i = tid; i < HW; i += TPB) {
                float c = b[i];
                bool peak = is_peak(b, i >> 8, i & 255, c);
                unsigned ball = __ballot_sync(0xFFFFFFFFu, peak);
                if (ball) {
                    int p;
                    if (lane == 0) p = atomicAdd(&g_cntB, __popc(ball));
                    p = __shfl_sync(0xFFFFFFFFu, p, 0);
                    if (peak) {
                        unsigned idx = ((unsigned)c2 << 16) | (unsigned)i;
                        g_candB[p + __popc(ball & ((1u << lane) - 1u))] =
                            ((unsigned long long)fkey(c) << 32) |
                            (unsigned long long)(~idx);
                    }
                }
            }
        }
        __syncthreads();
        const int nb = g_cntB;

        for (int i = tid; i < 4096; i += TPB) u.hist[i] = 0u;
        if (tid == 0) s_ng = 0;
        __syncthreads();
        for (int i = tid; i < nb; i += TPB)
            atomicAdd(&u.hist[(unsigned)(g_candB[i] >> 52)], 1u);
        __syncthreads();
        if (tid == 0) {
            unsigned acc = 0; int b = 4095;
            while (b > 0 && acc + u.hist[b] < (unsigned)TOPK_N) { acc += u.hist[b]; b--; }
            s_bin = b;
        }
        __syncthreads();
        const unsigned bin = (unsigned)s_bin;

        for (int i = tid; i < nb; i += TPB) {
            unsigned long long vv = g_candB[i];
            if ((unsigned)(vv >> 52) > bin) {
                int p = atomicAdd(&s_ng, 1);
                if (p < TOPK_N) s_sel[p] = vv;   // strictly-greater count < 100
            }
        }
        __syncthreads();
        int ng = min(s_ng, TOPK_N), need = TOPK_N - ng;
        unsigned long long lastv = ~0ULL;
        for (int pick = 0; pick < need; pick++) {
            if (tid == 0) s_best = 0ULL;
            __syncthreads();
            unsigned long long lb = 0ULL;
            for (int i = tid; i < nb; i += TPB) {
                unsigned long long vv = g_candB[i];
                if ((unsigned)(vv >> 52) == bin && vv < lastv && vv > lb) lb = vv;
            }
            atomicMax(&s_best, lb);
            __syncthreads();
            if (tid == 0) s_sel[ng + pick] = s_best;
            lastv = s_best;
            __syncthreads();
        }
        if (tid == 0) { g_cntA = 0; g_cntB = 0; g_done = 0; }
    }
    __syncthreads();

    // ---- decode + write ----
    if (tid < TOPK_N) {
        unsigned long long vv = s_sel[tid];
        int rank = 0;
        #pragma unroll 4
        for (int j = 0; j < TOPK_N; j++) rank += (s_sel[j] > vv);

        unsigned key = (unsigned)(vv >> 32);
        unsigned idx = ~(unsigned)(vv & 0xFFFFFFFFull);
        float raw    = fkey_inv(key);
        float score  = 1.0f / (1.0f + expf(-raw));
        int   cls_id = (int)(idx >> 16);
        int   sp     = (int)(idx & 0xFFFFu);     // y*256 + x
        int   yy     = sp >> 8;
        int   xx     = sp & 255;

        float tx = txty[sp];
        float ty = txty[HW + sp];
        float tw = twth[sp];
        float th = twth[HW + sp];

        // GS=1, STRIDE=4: xy = (grid + sigmoid(t)) * 4, wh = exp(t) * 4
        float cx = ((float)xx + 1.0f / (1.0f + expf(-tx))) * 4.0f;
        float cy = ((float)yy + 1.0f / (1.0f + expf(-ty))) * 4.0f;
        float w  = expf(tw) * 4.0f;
        float h  = expf(th) * 4.0f;

        const float inv = 1.0f / 1024.0f;
        float x1 = fminf(fmaxf((cx - 0.5f * w) * inv, 0.0f), 1.0f);
        float y1 = fminf(fmaxf((cy - 0.5f * h) * inv, 0.0f), 1.0f);
        float x2 = fminf(fmaxf((cx + 0.5f * w) * inv, 0.0f), 1.0f);
        float y2 = fminf(fmaxf((cy + 0.5f * h) * inv, 0.0f), 1.0f);

        out[rank * 4 + 0] = x1;
        out[rank * 4 + 1] = y1;
        out[rank * 4 + 2] = x2;
        out[rank * 4 + 3] = y2;
        out[400 + rank]   = score;
        out[500 + rank]   = (float)cls_id;
    }
}

// ---------------------------------------------------------------------------
extern "C" void kernel_launch(void* const* d_in, const int* in_sizes, int n_in,
                              void* d_out, int out_size) {
    const float* cls  = (const float*)d_in[0];   // [8,80,256,256]
    const float* txty = (const float*)d_in[1];   // [8,2,256,256]
    const float* twth = (const float*)d_in[2];   // [8,2,256,256]
    float* out = (float*)d_out;                  // 600 f32

    // per class: 16384 float4 / (256 threads * 8 per thread) = 8 blocks
    det_kernel<<<dim3(HW / 4 / (TPB * V4_PT), C_CLS), TPB>>>(cls, txty, twth, out);
}

// round 16
// speedup vs baseline: 1.0015x; 1.0015x over previous
#include <cuda_runtime.h>
#include <math_constants.h>
#include <cstdint>

// Problem shape (fixed per reference):
//   cls_pred  [8, 80, 256, 256] f32
//   txty_pred [8,  2, 256, 256] f32
//   twth_pred [8,  2, 256, 256] f32
// Output: bbox[100,4] | score[100] | cls[100]  -> 600 f32, batch 0 only.
//
// Exact algorithm: top-100 of suppressed scores == top-100 over 5x5-local-max
// peaks. Raw logits compared (sigmoid strictly monotone). Tier-A = peaks with
// logit > THR. If nA >= 100, the 100th-best peak > THR, so the true top-100
// is a subset of tier-A (checked at runtime). Otherwise an exact full-rescan
// fallback runs in the same kernel (P(nA<100) ~ 1e-40 for N(0,1) data).

#define C_CLS   80
#define H_DIM   256
#define W_DIM   256
#define HW      (H_DIM * W_DIM)       // 65536
#define N_ALL   (C_CLS * HW)          // 5242880
#define TOPK_N  100
#define THR     3.8f
#define SEL_CAP 2048
#define A_GCAP  65536
#define TPB     256

// Scratch. BSS zero-init; the selecting block resets counters at the end of
// every invocation, so each kernel_launch call is deterministic.
__device__ unsigned long long g_candA[A_GCAP];
__device__ unsigned long long g_candB[N_ALL];   // fallback only
__device__ int g_cntA, g_cntB, g_done;

// Order-preserving float -> unsigned transform.
__device__ __forceinline__ unsigned fkey(float f) {
    unsigned b = __float_as_uint(f);
    return (b & 0x80000000u) ? ~b : (b | 0x80000000u);
}
__device__ __forceinline__ float fkey_inv(unsigned k) {
    unsigned b = (k & 0x80000000u) ? (k & 0x7FFFFFFFu) : ~k;
    return __uint_as_float(b);
}

// Pixel (yy, xx) of plane `b` is a peak iff no 5x5 neighbor exceeds c.
__device__ __forceinline__ bool is_peak(const float* __restrict__ b,
                                        int yy, int xx, float c) {
    int ylo = max(yy - 2, 0), yhi = min(yy + 2, H_DIM - 1);
    int xlo = max(xx - 2, 0), xhi = min(xx + 2, W_DIM - 1);
    float m = -CUDART_INF_F;
    for (int ny = ylo; ny <= yhi; ny++) {
        const float* row = b + ny * W_DIM;
        for (int nx = xlo; nx <= xhi; nx++)
            m = fmaxf(m, row[nx]);   // includes self; c >= m <=> peak (ties kept)
    }
    return c >= m;
}

__global__ __launch_bounds__(TPB, 6)
void det_kernel(const float* __restrict__ cls,
                const float* __restrict__ txty,
                const float* __restrict__ twth,
                float* __restrict__ out) {
    __shared__ union {
        unsigned long long cand[SEL_CAP];   // select staging (last block only)
        unsigned           hist[4096];      // fallback scratch
    } u;
    __shared__ unsigned long long s_sel[TOPK_N];
    __shared__ unsigned long long s_best;
    __shared__ int s_last, s_ng, s_bin;

    const int tid  = threadIdx.x;
    const int lane = tid & 31;
    const int cid  = blockIdx.y;
    const float* __restrict__ base = cls + (size_t)cid * HW;
    const float4* __restrict__ base4 = (const float4*)base;

    // ---- phase 1: gated scan. 2 independent float4 loads per thread, one
    //      warp ballot per 256 pixels. Hit rate ~1.8% of warps. ----
    const int g0 = blockIdx.x * (TPB * 2) + tid;       // float4 index
    float4 a = __ldg(base4 + g0);
    float4 b = __ldg(base4 + g0 + TPB);
    float m8 = fmaxf(fmaxf(fmaxf(a.x, a.y), fmaxf(a.z, a.w)),
                     fmaxf(fmaxf(b.x, b.y), fmaxf(b.z, b.w)));

    if (__ballot_sync(0xFFFFFFFFu, m8 > THR)) {
        if (m8 > THR) {                                 // ~1-2 threads per hit warp
            float vals[8] = {a.x, a.y, a.z, a.w, b.x, b.y, b.z, b.w};
            unsigned long long loc[8];
            int cnt = 0;
            #pragma unroll
            for (int e = 0; e < 8; e++) {
                float c = vals[e];
                if (c > THR) {
                    int sp = (e < 4) ? (g0 * 4 + e) : ((g0 + TPB) * 4 + e - 4);
                    if (is_peak(base, sp >> 8, sp & 255, c)) {
                        unsigned idx = ((unsigned)cid << 16) | (unsigned)sp;
                        loc[cnt++] = ((unsigned long long)fkey(c) << 32) |
                                     (unsigned long long)(~idx);
                    }
                }
            }
            if (cnt) {
                int p = atomicAdd(&g_cntA, cnt);        // ~380 total, uncontended
                for (int i = 0; i < cnt; i++)
                    if (p + i < A_GCAP) g_candA[p + i] = loc[i];
            }
        }
    }

    // ---- last-block-done ticket ----
    __syncthreads();
    if (tid == 0) {
        __threadfence();
        int total = gridDim.x * gridDim.y;
        s_last = (atomicAdd(&g_done, 1) == total - 1) ? 1 : 0;
    }
    __syncthreads();
    if (!s_last) return;
    __threadfence();

    const int n = g_cntA;

    if (n >= TOPK_N && n <= SEL_CAP) {
        // ---- fast exact path: O(n^2/256) rank select over ~380 candidates ----
        for (int i = tid; i < n; i += TPB) u.cand[i] = g_candA[i];
        __syncthreads();
        for (int i = tid; i < n; i += TPB) {
            unsigned long long vv = u.cand[i];
            int rank = 0;
            for (int j = 0; j < n; j++) rank += (u.cand[j] > vv);
            if (rank < TOPK_N) s_sel[rank] = vv;
        }
        __syncthreads();
        if (tid == 0) { g_cntA = 0; g_done = 0; }
    } else {
        // ---- slow exact fallback (never taken for benchmark data) ----
        for (int c2 = 0; c2 < C_CLS; c2++) {
            const float* bb = cls + (size_t)c2 * HW;
            for (int i = tid; i < HW; i += TPB) {
                float c = bb[i];
                bool peak = is_peak(bb, i >> 8, i & 255, c);
                unsigned ball = __ballot_sync(0xFFFFFFFFu, peak);
                if (ball) {
                    int p;
                    if (lane == 0) p = atomicAdd(&g_cntB, __popc(ball));
                    p = __shfl_sync(0xFFFFFFFFu, p, 0);
                    if (peak) {
                        unsigned idx = ((unsigned)c2 << 16) | (unsigned)i;
                        g_candB[p + __popc(ball & ((1u << lane) - 1u))] =
                            ((unsigned long long)fkey(c) << 32) |
                            (unsigned long long)(~idx);
                    }
                }
            }
        }
        __syncthreads();
        const int nb = g_cntB;

        for (int i = tid; i < 4096; i += TPB) u.hist[i] = 0u;
        if (tid == 0) s_ng = 0;
        __syncthreads();
        for (int i = tid; i < nb; i += TPB)
            atomicAdd(&u.hist[(unsigned)(g_candB[i] >> 52)], 1u);
        __syncthreads();
        if (tid == 0) {
            unsigned acc = 0; int bi = 4095;
            while (bi > 0 && acc + u.hist[bi] < (unsigned)TOPK_N) { acc += u.hist[bi]; bi--; }
            s_bin = bi;
        }
        __syncthreads();
        const unsigned bin = (unsigned)s_bin;

        for (int i = tid; i < nb; i += TPB) {
            unsigned long long vv = g_candB[i];
            if ((unsigned)(vv >> 52) > bin) {
                int p = atomicAdd(&s_ng, 1);
                if (p < TOPK_N) s_sel[p] = vv;   // strictly-greater count < 100
            }
        }
        __syncthreads();
        int ng = min(s_ng, TOPK_N), need = TOPK_N - ng;
        unsigned long long lastv = ~0ULL;
        for (int pick = 0; pick < need; pick++) {
            if (tid == 0) s_best = 0ULL;
            __syncthreads();
            unsigned long long lb = 0ULL;
            for (int i = tid; i < nb; i += TPB) {
                unsigned long long vv = g_candB[i];
                if ((unsigned)(vv >> 52) == bin && vv < lastv && vv > lb) lb = vv;
            }
            atomicMax(&s_best, lb);
            __syncthreads();
            if (tid == 0) s_sel[ng + pick] = s_best;
            lastv = s_best;
            __syncthreads();
        }
        if (tid == 0) { g_cntA = 0; g_cntB = 0; g_done = 0; }
    }
    __syncthreads();

    // ---- decode + write ----
    if (tid < TOPK_N) {
        unsigned long long vv = s_sel[tid];
        int rank = 0;
        #pragma unroll 4
        for (int j = 0; j < TOPK_N; j++) rank += (s_sel[j] > vv);

        unsigned key = (unsigned)(vv >> 32);
        unsigned idx = ~(unsigned)(vv & 0xFFFFFFFFull);
        float raw    = fkey_inv(key);
        float score  = 1.0f / (1.0f + expf(-raw));
        int   cls_id = (int)(idx >> 16);
        int   sp     = (int)(idx & 0xFFFFu);     // y*256 + x
        int   yy     = sp >> 8;
        int   xx     = sp & 255;

        float tx = txty[sp];
        float ty = txty[HW + sp];
        float tw = twth[sp];
        float th = twth[HW + sp];

        // GS=1, STRIDE=4: xy = (grid + sigmoid(t)) * 4, wh = exp(t) * 4
        float cx = ((float)xx + 1.0f / (1.0f + expf(-tx))) * 4.0f;
        float cy = ((float)yy + 1.0f / (1.0f + expf(-ty))) * 4.0f;
        float w  = expf(tw) * 4.0f;
        float h  = expf(th) * 4.0f;

        const float inv = 1.0f / 1024.0f;
        float x1 = fminf(fmaxf((cx - 0.5f * w) * inv, 0.0f), 1.0f);
        float y1 = fminf(fmaxf((cy - 0.5f * h) * inv, 0.0f), 1.0f);
        float x2 = fminf(fmaxf((cx + 0.5f * w) * inv, 0.0f), 1.0f);
        float y2 = fminf(fmaxf((cy + 0.5f * h) * inv, 0.0f), 1.0f);

        out[rank * 4 + 0] = x1;
        out[rank * 4 + 1] = y1;
        out[rank * 4 + 2] = x2;
        out[rank * 4 + 3] = y2;
        out[400 + rank]   = score;
        out[500 + rank]   = (float)cls_id;
    }
}

// ---------------------------------------------------------------------------
extern "C" void kernel_launch(void* const* d_in, const int* in_sizes, int n_in,
                              void* d_out, int out_size) {
    const float* cls  = (const float*)d_in[0];   // [8,80,256,256]
    const float* txty = (const float*)d_in[1];   // [8,2,256,256]
    const float* twth = (const float*)d_in[2];   // [8,2,256,256]
    float* out = (float*)d_out;                  // 600 f32

    // per class: 16384 float4 / (256 threads * 2 per thread) = 32 blocks
    det_kernel<<<dim3(HW / 4 / (TPB * 2), C_CLS), TPB>>>(cls, txty, twth, out);
}